// round 12
// baseline (speedup 1.0000x reference)
#include <cuda_runtime.h>
#include <cuda_fp16.h>
#include <cuda.h>
#include <cstdint>
#include <cstdio>
#include <dlfcn.h>

// ---------------------------------------------------------------------------
// out = SiLU(x)@Wb^T + einsum('bik,oik->bo', basis(x), Ws) as a 2:4-sparse
// GEMM via mma.sp::ordered_metadata.m16n8k32:
//   logical K'=10240: [0,2048) silu padded [s,0,s',0]; [2048,10240) spline,
//   per input i 8 slots = even basis {b0,b2,b4,b6} then odd {b1,b3,b5,b7}.
//   Cubic support iv..iv+3 => exactly 2 nonzeros per 4-chunk, at (p, p+1).
//   Compressed K = 5120. Metadata layout probed at runtime.
// R12: 16 consumer warps (4/SMSP) + TMA producer -- R11 ncu showed the sparse
// pipe at 36% with issue 30%/occ 14%: latency-bound, not tensor-bound.
// ---------------------------------------------------------------------------
#define B_ROWS 8192
#define IN_F   1024
#define OUT_F  1024
#define KLOG   10240
#define KCOMP  5120

__device__ __align__(1024) __half   g_Ac[(size_t)B_ROWS * KCOMP];  // 80 MB
__device__ __align__(1024) __half   g_Wl[(size_t)OUT_F * KLOG];    // 20 MB
__device__ __align__(1024) uint32_t g_M32[(size_t)512 * 8 * (KLOG / 16)]; // 10.5 MB
__device__ int g_meta_mode;

// ===========================================================================
// PTX helpers
// ===========================================================================
__device__ __forceinline__ uint32_t smem_u32(const void* p) {
    uint32_t a;
    asm("{ .reg .u64 t; cvta.to.shared.u64 t, %1; cvt.u32.u64 %0, t; }" : "=r"(a) : "l"(p));
    return a;
}
__device__ __forceinline__ uint32_t elect_one() {
    uint32_t pred;
    asm volatile("{\n .reg .pred p;\n elect.sync _|p, 0xFFFFFFFF;\n selp.b32 %0, 1, 0, p;\n}" : "=r"(pred));
    return pred;
}
#define MBAR_INIT(addr, cnt) \
    asm volatile("mbarrier.init.shared.b64 [%0], %1;" :: "r"(addr), "r"((uint32_t)(cnt)) : "memory")
#define MBAR_EXPECT_TX(addr, bytes) \
    asm volatile("mbarrier.arrive.expect_tx.shared.b64 _, [%0], %1;" :: "r"(addr), "r"((uint32_t)(bytes)) : "memory")
#define MBAR_ARRIVE(addr) \
    asm volatile("mbarrier.arrive.shared.b64 _, [%0];" :: "r"(addr) : "memory")
#define MBAR_WAIT(addr, parity) do {                                          \
    uint32_t _m = (addr); uint32_t _p = (parity); uint32_t _d;                \
    asm volatile("{\n .reg .pred p;\n"                                        \
        " mbarrier.try_wait.parity.acquire.cta.shared::cta.b64 p, [%1], %2;\n"\
        " selp.b32 %0, 1, 0, p;\n}" : "=r"(_d) : "r"(_m), "r"(_p) : "memory");\
    if (!_d) {                                                                \
        asm volatile("{\n .reg .pred P1;\n"                                   \
        "WL_%=:\n"                                                            \
        " mbarrier.try_wait.parity.acquire.cta.shared::cta.b64 P1, [%0], %1, 0x989680;\n" \
        " @P1 bra.uni WD_%=;\n bra.uni WL_%=;\nWD_%=:\n}"                     \
        :: "r"(_m), "r"(_p) : "memory");                                      \
    } } while (0)

__device__ __forceinline__ void tma_load_2d(uint32_t dst, const void* map,
                                            int cx, int cy, uint32_t mbar) {
    asm volatile(
        "cp.async.bulk.tensor.2d.shared::cta.global.tile.mbarrier::complete_tx::bytes "
        "[%0], [%1, {%2, %3}], [%4];"
        :: "r"(dst), "l"(map), "r"(cx), "r"(cy), "r"(mbar) : "memory");
}
__device__ __forceinline__ void ldsm_x4(uint32_t* r, uint32_t addr) {
    asm volatile("ldmatrix.sync.aligned.m8n8.x4.shared.b16 {%0,%1,%2,%3}, [%4];"
        : "=r"(r[0]), "=r"(r[1]), "=r"(r[2]), "=r"(r[3]) : "r"(addr));
}
__device__ __forceinline__ void mma_sp0(float* c, const uint32_t* a, const uint32_t* b, uint32_t e) {
    asm volatile(
        "mma.sp::ordered_metadata.sync.aligned.m16n8k32.row.col.f32.f16.f16.f32 "
        "{%0,%1,%2,%3}, {%4,%5,%6,%7}, {%8,%9,%10,%11}, {%0,%1,%2,%3}, %12, 0x0;\n"
        : "+f"(c[0]), "+f"(c[1]), "+f"(c[2]), "+f"(c[3])
        : "r"(a[0]), "r"(a[1]), "r"(a[2]), "r"(a[3]),
          "r"(b[0]), "r"(b[1]), "r"(b[2]), "r"(b[3]), "r"(e));
}
__device__ __forceinline__ void mma_sp1(float* c, const uint32_t* a, const uint32_t* b, uint32_t e) {
    asm volatile(
        "mma.sp::ordered_metadata.sync.aligned.m16n8k32.row.col.f32.f16.f16.f32 "
        "{%0,%1,%2,%3}, {%4,%5,%6,%7}, {%8,%9,%10,%11}, {%0,%1,%2,%3}, %12, 0x1;\n"
        : "+f"(c[0]), "+f"(c[1]), "+f"(c[2]), "+f"(c[3])
        : "r"(a[0]), "r"(a[1]), "r"(a[2]), "r"(a[3]),
          "r"(b[0]), "r"(b[1]), "r"(b[2]), "r"(b[3]), "r"(e));
}
// m0 = packed word (row q | row q+8 <<16) for kword 2ks (k0-15), m1 for 2ks+1.
__device__ __forceinline__ uint32_t assemble_e(int mode, uint32_t m0, uint32_t m1, int tb) {
    if (mode == 1) return tb ? ((m0 >> 16) | (m1 & 0xFFFF0000u))
                             : ((m0 & 0xFFFFu) | (m1 << 16));
    if (mode == 2) { uint32_t m = tb ? m1 : m0; return (m >> 16) | (m << 16); }
    if (mode == 3) return tb ? m0 : m1;
    return tb ? m1 : m0;   // modes 0 and 4
}

// ===========================================================================
// Probe: discover metadata layout. A=1s, B[k][n]=k+1, meta idx p=(r+c)%3.
// Expected D[r] = sum_c (8c + 2p + 3).
// ===========================================================================
__device__ __forceinline__ uint32_t probe_M16(int r, int w) {
    uint32_t m = 0;
#pragma unroll
    for (int cc = 0; cc < 4; cc++) {
        int c = 4 * w + cc;
        uint32_t p = (uint32_t)((r + c) % 3);
        m |= (p | ((p + 1) << 2)) << (4 * cc);
    }
    return m;
}
__global__ void probe_kernel() {
    int lane = threadIdx.x;
    int q = lane >> 2, t = lane & 3, tb = t & 1;
    uint32_t a[4] = {0x3C003C00u, 0x3C003C00u, 0x3C003C00u, 0x3C003C00u};
    uint32_t b[4];
#pragma unroll
    for (int r = 0; r < 4; r++) {
        int k0 = 2 * t + ((r & 1) ? 8 : 0) + ((r >> 1) ? 16 : 0);
        __half2 h = __floats2half2_rn((float)(k0 + 1), (float)(k0 + 2));
        b[r] = *reinterpret_cast<uint32_t*>(&h);
    }
    float S0 = 0.0f, S1 = 0.0f;
#pragma unroll
    for (int c = 0; c < 8; c++) {
        S0 += (float)(8 * c + 2 * ((q + c) % 3) + 3);
        S1 += (float)(8 * c + 2 * ((q + 8 + c) % 3) + 3);
    }
    uint32_t m0 = probe_M16(q, 0) | (probe_M16(q + 8, 0) << 16);
    uint32_t m1 = probe_M16(q, 1) | (probe_M16(q + 8, 1) << 16);
    int found = -1;
#pragma unroll 1
    for (int H = 0; H < 5; H++) {
        uint32_t e = assemble_e(H, m0, m1, tb);
        float d[4] = {0.0f, 0.0f, 0.0f, 0.0f};
        if (H == 4) mma_sp1(d, a, b, e); else mma_sp0(d, a, b, e);
        bool ok = (d[0] == S0) && (d[1] == S0) && (d[2] == S1) && (d[3] == S1);
        if (__all_sync(0xFFFFFFFFu, ok) && found < 0) found = H;
    }
    if (lane == 0) {
        g_meta_mode = (found < 0) ? 0 : found;
        printf("[probe] meta mode = %d\n", found);
    }
}

// ===========================================================================
// Prep: closed-form cubic B-spline (nonzero taps N0..N3 on interval iv)
// ===========================================================================
struct SB { float s, ev0, ev1, od0, od1; int pe, po; };
__device__ __forceinline__ SB eval_point(float v) {
    SB r;
    r.s = v / (1.0f + __expf(-v));
    float xc = fminf(fmaxf(v, -1.0f), 1.0f);
    float t = (xc + 1.0f) * 2.5f;
    int iv = (int)t; if (iv > 4) iv = 4;
    float u = t - (float)iv;
    float um = 1.0f - u;
    float u2 = u * u, u3 = u2 * u;
    float N0 = um * um * um * 0.16666667f;
    float N1 = 0.5f * u3 - u2 + 0.66666667f;
    float N2 = -0.5f * u3 + 0.5f * u2 + 0.5f * u + 0.16666667f;
    float N3 = u3 * 0.16666667f;
    if (iv & 1) { r.ev0 = N1; r.ev1 = N3; r.od0 = N0; r.od1 = N2; }
    else        { r.ev0 = N0; r.ev1 = N2; r.od0 = N1; r.od1 = N3; }
    r.pe = (iv + 1) >> 1;
    r.po = iv >> 1;
    return r;
}
__device__ __forceinline__ uint32_t meta_byte(const SB& e) {
    uint32_t nE = (uint32_t)e.pe | ((uint32_t)(e.pe + 1) << 2);
    uint32_t nO = (uint32_t)e.po | ((uint32_t)(e.po + 1) << 2);
    return nE | (nO << 4);
}

// thread -> (g 0..511, q 0..7, c 0..511): rows 16g+q, 16g+q+8; inputs 2c,2c+1
__global__ void prep_A_kernel(const float* __restrict__ x) {
    int idx = blockIdx.x * blockDim.x + threadIdx.x;
    if (idx >= 512 * 8 * 512) return;
    int c = idx & 511;
    int q = (idx >> 9) & 7;
    int g = idx >> 12;
    uint32_t w16[2];
#pragma unroll
    for (int h = 0; h < 2; h++) {
        int r = 16 * g + q + 8 * h;
        float2 xv = reinterpret_cast<const float2*>(x)[(size_t)r * 512 + c];
        SB e0 = eval_point(xv.x);
        SB e1 = eval_point(xv.y);
        __half* rowp = g_Ac + (size_t)r * KCOMP;
        __half2 hs = __floats2half2_rn(e0.s, e1.s);
        reinterpret_cast<uint32_t*>(rowp)[c] = *reinterpret_cast<uint32_t*>(&hs);
        __align__(16) __half2 hv[4];
        hv[0] = __floats2half2_rn(e0.ev0, e0.ev1);
        hv[1] = __floats2half2_rn(e0.od0, e0.od1);
        hv[2] = __floats2half2_rn(e1.ev0, e1.ev1);
        hv[3] = __floats2half2_rn(e1.od0, e1.od1);
        reinterpret_cast<uint4*>(rowp + 1024)[c] = *reinterpret_cast<uint4*>(hv);
        w16[h] = meta_byte(e0) | (meta_byte(e1) << 8);
    }
    size_t mbase = ((size_t)g * 8 + q) * (KLOG / 16);
    g_M32[mbase + 128 + c] = w16[0] | (w16[1] << 16);
    if (c < 128) g_M32[mbase + c] = 0x88888888u;   // silu: idx (0,2) everywhere
}

// thread -> (o, c 0..511): silu chunk c + spline inputs 2c, 2c+1
__global__ void prep_W_kernel(const float* __restrict__ base_w,
                              const float* __restrict__ spline_w) {
    int idx = blockIdx.x * blockDim.x + threadIdx.x;
    if (idx >= OUT_F * 512) return;
    int c = idx & 511;
    int o = idx >> 9;
    __half* rowp = g_Wl + (size_t)o * KLOG;
    float2 bw = reinterpret_cast<const float2*>(base_w)[(size_t)o * 512 + c];
    __align__(8) __half h4[4];
    h4[0] = __float2half_rn(bw.x); h4[1] = __ushort_as_half(0);
    h4[2] = __float2half_rn(bw.y); h4[3] = __ushort_as_half(0);
    reinterpret_cast<uint2*>(rowp)[c] = *reinterpret_cast<uint2*>(h4);
#pragma unroll
    for (int h = 0; h < 2; h++) {
        int i = 2 * c + h;
        const float4* sp = reinterpret_cast<const float4*>(spline_w + ((size_t)o * IN_F + i) * 8);
        float4 v0 = sp[0], v1 = sp[1];
        float s[8] = {v0.x, v0.y, v0.z, v0.w, v1.x, v1.y, v1.z, v1.w};
        __align__(16) __half h8[8];
        h8[0] = __float2half_rn(s[0]); h8[1] = __float2half_rn(s[2]);
        h8[2] = __float2half_rn(s[4]); h8[3] = __float2half_rn(s[6]);
        h8[4] = __float2half_rn(s[1]); h8[5] = __float2half_rn(s[3]);
        h8[6] = __float2half_rn(s[5]); h8[7] = __float2half_rn(s[7]);
        reinterpret_cast<uint4*>(rowp + 2048)[i] = *reinterpret_cast<uint4*>(h8);
    }
}

// ===========================================================================
// Sparse GEMM: TMA producer + 16 consumer warps (4/SMSP), 4-stage ring.
// Stage = 128 logical k: A 64 compressed halves/row (128B SW128),
// B two 64-half sub-tiles. Warp tile 32x32.
// ===========================================================================
#define BM 128
#define BN 128
#define NSTG 4
#define NKS (KLOG / 128)                      // 80
#define A_BYTES (BM * 64 * 2)                 // 16384
#define B_BYTES (BN * 128 * 2)                // 32768
#define STG_BYTES (A_BYTES + B_BYTES)         // 49152
#define SMEM_BARS 1024
#define SMEM_TOTAL (SMEM_BARS + NSTG * STG_BYTES)   // 197632

__global__ void __launch_bounds__(544, 1) gemm_kernel(
    const __grid_constant__ CUtensorMap tmA,
    const __grid_constant__ CUtensorMap tmB,
    float* __restrict__ C)
{
    extern __shared__ __align__(1024) char smem[];
    const uint32_t sb = smem_u32(smem);
    const uint32_t FULL  = sb;
    const uint32_t EMPTY = sb + 64;
    const uint32_t STG0  = sb + SMEM_BARS;

    const int tid = threadIdx.x;
    const int wid = tid >> 5;
    const int lane = tid & 31;
    const int bm = blockIdx.y;
    const int bn = blockIdx.x;

    if (tid == 0) {
#pragma unroll
        for (int s = 0; s < NSTG; s++) {
            MBAR_INIT(FULL + 8 * s, 1);
            MBAR_INIT(EMPTY + 8 * s, 16);
        }
    }
    __syncthreads();

    if (wid == 16) {
        if (elect_one()) {
            int st = 0, ph = 1;
            for (int s = 0; s < NKS; s++) {
                MBAR_WAIT(EMPTY + 8 * st, ph);
                const uint32_t buf = STG0 + st * STG_BYTES;
                MBAR_EXPECT_TX(FULL + 8 * st, STG_BYTES);
                tma_load_2d(buf, &tmA, s * 64, bm * BM, FULL + 8 * st);
                tma_load_2d(buf + A_BYTES, &tmB, s * 128, bn * BN, FULL + 8 * st);
                tma_load_2d(buf + A_BYTES + 16384, &tmB, s * 128 + 64, bn * BN, FULL + 8 * st);
                if (++st == NSTG) { st = 0; ph ^= 1; }
            }
        }
        return;
    }

    // consumers (warps 0..15): wm 4 x 32 (M), wn 4 x 32 (N)
    const int grp = lane >> 2;
    const int thr = lane & 3;
    const int tb = lane & 1;
    const int q = lane >> 2;
    const int wm = (wid & 3) * 32;
    const int wn = (wid >> 2) * 32;
    const int mmode = g_meta_mode;
    const bool sel1 = (mmode == 4);

    const int hiA = lane >> 4;
    const int hiB = (lane >> 3) & 1;
    uint32_t aoff[2]; int ax7[2];
#pragma unroll
    for (int im = 0; im < 2; im++) {
        int r = wm + (lane & 15) + im * 16;
        aoff[im] = (uint32_t)r * 128;
        ax7[im] = r & 7;
    }
    uint32_t boff[2]; int bx7[2];
#pragma unroll
    for (int p = 0; p < 2; p++) {
        int r = wn + p * 16 + ((lane >> 4) << 3) + (lane & 7);
        boff[p] = (uint32_t)r * 128;
        bx7[p] = r & 7;
    }
    size_t mbase[2];
#pragma unroll
    for (int im = 0; im < 2; im++) {
        int g = bm * 8 + 2 * (wid & 3) + im;
        mbase[im] = ((size_t)g * 8 + q) * (KLOG / 16);
    }

    float acc[2][4][4];
#pragma unroll
    for (int im = 0; im < 2; im++)
#pragma unroll
        for (int in = 0; in < 4; in++)
#pragma unroll
            for (int r = 0; r < 4; r++) acc[im][in][r] = 0.0f;

    int st = 0, ph = 0;
#pragma unroll 1
    for (int s = 0; s < NKS; s++) {
        uint32_t mw[2][8];
#pragma unroll
        for (int im = 0; im < 2; im++) {
            const uint4* p4 = reinterpret_cast<const uint4*>(&g_M32[mbase[im] + (size_t)s * 8]);
            uint4 v0 = __ldg(p4), v1 = __ldg(p4 + 1);
            mw[im][0] = v0.x; mw[im][1] = v0.y; mw[im][2] = v0.z; mw[im][3] = v0.w;
            mw[im][4] = v1.x; mw[im][5] = v1.y; mw[im][6] = v1.z; mw[im][7] = v1.w;
        }
        MBAR_WAIT(FULL + 8 * st, ph);
        const uint32_t bufA = STG0 + st * STG_BYTES;
        const uint32_t bufB = bufA + A_BYTES;
#pragma unroll
        for (int ks = 0; ks < 4; ks++) {
            const int cba = 2 * ks;
            uint32_t af[2][4];
#pragma unroll
            for (int im = 0; im < 2; im++)
                ldsm_x4(af[im], bufA + aoff[im] +
                        (uint32_t)(((cba + hiA) ^ ax7[im]) << 4));
            const uint32_t bufBs = bufB + (uint32_t)(ks >> 1) * 16384;
            const int cbl = 4 * (ks & 1);
            uint32_t bq0[2][4], bq1[2][4];
#pragma unroll
            for (int p = 0; p < 2; p++) {
                ldsm_x4(bq0[p], bufBs + boff[p] +
                        (uint32_t)(((cbl + hiB) ^ bx7[p]) << 4));
                ldsm_x4(bq1[p], bufBs + boff[p] +
                        (uint32_t)(((cbl + 2 + hiB) ^ bx7[p]) << 4));
            }
            uint32_t e0 = assemble_e(mmode, mw[0][2 * ks], mw[0][2 * ks + 1], tb);
            uint32_t e1 = assemble_e(mmode, mw[1][2 * ks], mw[1][2 * ks + 1], tb);
#pragma unroll
            for (int p = 0; p < 2; p++) {
                uint32_t bA[4] = {bq0[p][0], bq0[p][1], bq1[p][0], bq1[p][1]};
                uint32_t bB[4] = {bq0[p][2], bq0[p][3], bq1[p][2], bq1[p][3]};
                if (!sel1) {
                    mma_sp0(acc[0][2 * p + 0], af[0], bA, e0);
                    mma_sp0(acc[0][2 * p + 1], af[0], bB, e0);
                    mma_sp0(acc[1][2 * p + 0], af[1], bA, e1);
                    mma_sp0(acc[1][2 * p + 1], af[1], bB, e1);
                } else {
                    mma_sp1(acc[0][2 * p + 0], af[0], bA, e0);
                    mma_sp1(acc[0][2 * p + 1], af[0], bB, e0);
                    mma_sp1(acc[1][2 * p + 0], af[1], bA, e1);
                    mma_sp1(acc[1][2 * p + 1], af[1], bB, e1);
                }
            }
        }
        if (lane == 0) MBAR_ARRIVE(EMPTY + 8 * st);
        if (++st == NSTG) { st = 0; ph ^= 1; }
    }

    // epilogue
#pragma unroll
    for (int im = 0; im < 2; im++) {
        int row0 = bm * BM + wm + im * 16 + grp;
#pragma unroll
        for (int in = 0; in < 4; in++) {
            int col = bn * BN + wn + in * 8 + thr * 2;
            float2 v0 = make_float2(acc[im][in][0], acc[im][in][1]);
            float2 v1 = make_float2(acc[im][in][2], acc[im][in][3]);
            *(float2*)&C[(size_t)row0 * OUT_F + col] = v0;
            *(float2*)&C[(size_t)(row0 + 8) * OUT_F + col] = v1;
        }
    }
}

// ===========================================================================
// Host side
// ===========================================================================
typedef CUresult (*EncodeTiledFn)(
    CUtensorMap*, CUtensorMapDataType, cuuint32_t, void*,
    const cuuint64_t*, const cuuint64_t*, const cuuint32_t*, const cuuint32_t*,
    CUtensorMapInterleave, CUtensorMapSwizzle, CUtensorMapL2promotion,
    CUtensorMapFloatOOBfill);

static EncodeTiledFn get_encode_fn() {
    static EncodeTiledFn fn = nullptr;
    if (!fn) {
        void* h = dlopen("libcuda.so.1", RTLD_NOW | RTLD_GLOBAL);
        if (!h) h = dlopen("libcuda.so", RTLD_NOW | RTLD_GLOBAL);
        if (h) fn = (EncodeTiledFn)dlsym(h, "cuTensorMapEncodeTiled");
    }
    return fn;
}

static void make_map(CUtensorMap* map, void* base, uint64_t kdim, uint64_t rows,
                     uint32_t box_rows) {
    cuuint64_t dims[2]    = {(cuuint64_t)kdim, (cuuint64_t)rows};
    cuuint64_t strides[1] = {(cuuint64_t)kdim * sizeof(__half)};
    cuuint32_t box[2]     = {64u, box_rows};
    cuuint32_t estr[2]    = {1, 1};
    get_encode_fn()(map, CU_TENSOR_MAP_DATA_TYPE_FLOAT16, 2, base,
                    dims, strides, box, estr,
                    CU_TENSOR_MAP_INTERLEAVE_NONE, CU_TENSOR_MAP_SWIZZLE_128B,
                    CU_TENSOR_MAP_L2_PROMOTION_L2_128B,
                    CU_TENSOR_MAP_FLOAT_OOB_FILL_NONE);
}

extern "C" void kernel_launch(void* const* d_in, const int* in_sizes, int n_in,
                              void* d_out, int out_size) {
    const float* x        = (const float*)d_in[0];   // (8192, 1024)
    const float* base_w   = (const float*)d_in[1];   // (1024, 1024)
    const float* spline_w = (const float*)d_in[2];   // (1024, 1024, 8)
    float* out            = (float*)d_out;           // (8192, 1024)

    void *pA = nullptr, *pW = nullptr;
    cudaGetSymbolAddress(&pA, g_Ac);
    cudaGetSymbolAddress(&pW, g_Wl);

    CUtensorMap tmA, tmB;
    make_map(&tmA, pA, KCOMP, B_ROWS, BM);
    make_map(&tmB, pW, KLOG, OUT_F, BN);

    cudaFuncSetAttribute(gemm_kernel,
                         cudaFuncAttributeMaxDynamicSharedMemorySize, SMEM_TOTAL);

    probe_kernel<<<1, 32>>>();
    prep_W_kernel<<<(OUT_F * 512 + 255) / 256, 256>>>(base_w, spline_w);
    prep_A_kernel<<<(512 * 8 * 512 + 255) / 256, 256>>>(x);

    dim3 grid(OUT_F / BN, B_ROWS / BM);   // (8, 64)
    gemm_kernel<<<grid, 544, SMEM_TOTAL>>>(tmA, tmB, out);
}

// round 17
// speedup vs baseline: 1.3275x; 1.3275x over previous
#include <cuda_runtime.h>
#include <cuda_fp16.h>
#include <cuda.h>
#include <cstdint>
#include <cstdio>
#include <dlfcn.h>

// ---------------------------------------------------------------------------
// out = SiLU(x)@Wb^T + einsum('bik,oik->bo', basis(x), Ws) as a 2:4-sparse
// GEMM (mma.sp::ordered_metadata.m16n8k32). Logical K'=10240, compressed 5120.
// R13: LDSM-balanced warp tile 64x32 (2M x 4N groups) + metadata pre-assembled
// into per-thread e-words by prep_E (zero meta ALU in mainloop).
// ---------------------------------------------------------------------------
#define B_ROWS 8192
#define IN_F   1024
#define OUT_F  1024
#define KLOG   10240
#define KCOMP  5120
#define NKS    (KLOG / 128)                   // 80 stages

__device__ __align__(1024) __half   g_Ac[(size_t)B_ROWS * KCOMP];  // 80 MB
__device__ __align__(1024) __half   g_Wl[(size_t)OUT_F * KLOG];    // 20 MB
__device__ __align__(1024) uint32_t g_M32[(size_t)512 * 8 * (KLOG / 16)]; // 10.5 MB
__device__ __align__(1024) uint4    g_E[(size_t)512 * 8 * NKS * 2];       // 10.5 MB
__device__ int g_meta_mode;

template <int V> struct IC { static constexpr int value = V; };

// ===========================================================================
// PTX helpers
// ===========================================================================
__device__ __forceinline__ uint32_t smem_u32(const void* p) {
    uint32_t a;
    asm("{ .reg .u64 t; cvta.to.shared.u64 t, %1; cvt.u32.u64 %0, t; }" : "=r"(a) : "l"(p));
    return a;
}
__device__ __forceinline__ uint32_t elect_one() {
    uint32_t pred;
    asm volatile("{\n .reg .pred p;\n elect.sync _|p, 0xFFFFFFFF;\n selp.b32 %0, 1, 0, p;\n}" : "=r"(pred));
    return pred;
}
#define MBAR_INIT(addr, cnt) \
    asm volatile("mbarrier.init.shared.b64 [%0], %1;" :: "r"(addr), "r"((uint32_t)(cnt)) : "memory")
#define MBAR_EXPECT_TX(addr, bytes) \
    asm volatile("mbarrier.arrive.expect_tx.shared.b64 _, [%0], %1;" :: "r"(addr), "r"((uint32_t)(bytes)) : "memory")
#define MBAR_ARRIVE(addr) \
    asm volatile("mbarrier.arrive.shared.b64 _, [%0];" :: "r"(addr) : "memory")
#define MBAR_WAIT(addr, parity) do {                                          \
    uint32_t _m = (addr); uint32_t _p = (parity); uint32_t _d;                \
    asm volatile("{\n .reg .pred p;\n"                                        \
        " mbarrier.try_wait.parity.acquire.cta.shared::cta.b64 p, [%1], %2;\n"\
        " selp.b32 %0, 1, 0, p;\n}" : "=r"(_d) : "r"(_m), "r"(_p) : "memory");\
    if (!_d) {                                                                \
        asm volatile("{\n .reg .pred P1;\n"                                   \
        "WL_%=:\n"                                                            \
        " mbarrier.try_wait.parity.acquire.cta.shared::cta.b64 P1, [%0], %1, 0x989680;\n" \
        " @P1 bra.uni WD_%=;\n bra.uni WL_%=;\nWD_%=:\n}"                     \
        :: "r"(_m), "r"(_p) : "memory");                                      \
    } } while (0)

__device__ __forceinline__ void tma_load_2d(uint32_t dst, const void* map,
                                            int cx, int cy, uint32_t mbar) {
    asm volatile(
        "cp.async.bulk.tensor.2d.shared::cta.global.tile.mbarrier::complete_tx::bytes "
        "[%0], [%1, {%2, %3}], [%4];"
        :: "r"(dst), "l"(map), "r"(cx), "r"(cy), "r"(mbar) : "memory");
}
__device__ __forceinline__ void ldsm_x4(uint32_t* r, uint32_t addr) {
    asm volatile("ldmatrix.sync.aligned.m8n8.x4.shared.b16 {%0,%1,%2,%3}, [%4];"
        : "=r"(r[0]), "=r"(r[1]), "=r"(r[2]), "=r"(r[3]) : "r"(addr));
}
__device__ __forceinline__ void mma_sp0(float* c, const uint32_t* a, const uint32_t* b, uint32_t e) {
    asm volatile(
        "mma.sp::ordered_metadata.sync.aligned.m16n8k32.row.col.f32.f16.f16.f32 "
        "{%0,%1,%2,%3}, {%4,%5,%6,%7}, {%8,%9,%10,%11}, {%0,%1,%2,%3}, %12, 0x0;\n"
        : "+f"(c[0]), "+f"(c[1]), "+f"(c[2]), "+f"(c[3])
        : "r"(a[0]), "r"(a[1]), "r"(a[2]), "r"(a[3]),
          "r"(b[0]), "r"(b[1]), "r"(b[2]), "r"(b[3]), "r"(e));
}
__device__ __forceinline__ void mma_sp1(float* c, const uint32_t* a, const uint32_t* b, uint32_t e) {
    asm volatile(
        "mma.sp::ordered_metadata.sync.aligned.m16n8k32.row.col.f32.f16.f16.f32 "
        "{%0,%1,%2,%3}, {%4,%5,%6,%7}, {%8,%9,%10,%11}, {%0,%1,%2,%3}, %12, 0x1;\n"
        : "+f"(c[0]), "+f"(c[1]), "+f"(c[2]), "+f"(c[3])
        : "r"(a[0]), "r"(a[1]), "r"(a[2]), "r"(a[3]),
          "r"(b[0]), "r"(b[1]), "r"(b[2]), "r"(b[3]), "r"(e));
}
template <int SEL>
__device__ __forceinline__ void mma_sp_t(float* c, const uint32_t* a, const uint32_t* b, uint32_t e) {
    if (SEL) mma_sp1(c, a, b, e); else mma_sp0(c, a, b, e);
}
// m0 = packed word (row q | row q+8 <<16) for kword 2ks, m1 for 2ks+1.
__device__ __forceinline__ uint32_t assemble_e(int mode, uint32_t m0, uint32_t m1, int tb) {
    if (mode == 1) return tb ? ((m0 >> 16) | (m1 & 0xFFFF0000u))
                             : ((m0 & 0xFFFFu) | (m1 << 16));
    if (mode == 2) { uint32_t m = tb ? m1 : m0; return (m >> 16) | (m << 16); }
    if (mode == 3) return tb ? m0 : m1;
    return tb ? m1 : m0;   // modes 0 and 4
}

// ===========================================================================
// Probe: discover metadata layout (validated in R11/R12).
// ===========================================================================
__device__ __forceinline__ uint32_t probe_M16(int r, int w) {
    uint32_t m = 0;
#pragma unroll
    for (int cc = 0; cc < 4; cc++) {
        int c = 4 * w + cc;
        uint32_t p = (uint32_t)((r + c) % 3);
        m |= (p | ((p + 1) << 2)) << (4 * cc);
    }
    return m;
}
__global__ void probe_kernel() {
    int lane = threadIdx.x;
    int q = lane >> 2, t = lane & 3, tb = t & 1;
    uint32_t a[4] = {0x3C003C00u, 0x3C003C00u, 0x3C003C00u, 0x3C003C00u};
    uint32_t b[4];
#pragma unroll
    for (int r = 0; r < 4; r++) {
        int k0 = 2 * t + ((r & 1) ? 8 : 0) + ((r >> 1) ? 16 : 0);
        __half2 h = __floats2half2_rn((float)(k0 + 1), (float)(k0 + 2));
        b[r] = *reinterpret_cast<uint32_t*>(&h);
    }
    float S0 = 0.0f, S1 = 0.0f;
#pragma unroll
    for (int c = 0; c < 8; c++) {
        S0 += (float)(8 * c + 2 * ((q + c) % 3) + 3);
        S1 += (float)(8 * c + 2 * ((q + 8 + c) % 3) + 3);
    }
    uint32_t m0 = probe_M16(q, 0) | (probe_M16(q + 8, 0) << 16);
    uint32_t m1 = probe_M16(q, 1) | (probe_M16(q + 8, 1) << 16);
    int found = -1;
#pragma unroll 1
    for (int H = 0; H < 5; H++) {
        uint32_t e = assemble_e(H, m0, m1, tb);
        float d[4] = {0.0f, 0.0f, 0.0f, 0.0f};
        if (H == 4) mma_sp1(d, a, b, e); else mma_sp0(d, a, b, e);
        bool ok = (d[0] == S0) && (d[1] == S0) && (d[2] == S1) && (d[3] == S1);
        if (__all_sync(0xFFFFFFFFu, ok) && found < 0) found = H;
    }
    if (lane == 0) {
        g_meta_mode = (found < 0) ? 0 : found;
        printf("[probe] meta mode = %d\n", found);
    }
}

// ===========================================================================
// Prep (validated in R11/R12): closed-form cubic B-spline, sparse A + meta.
// ===========================================================================
struct SB { float s, ev0, ev1, od0, od1; int pe, po; };
__device__ __forceinline__ SB eval_point(float v) {
    SB r;
    r.s = v / (1.0f + __expf(-v));
    float xc = fminf(fmaxf(v, -1.0f), 1.0f);
    float t = (xc + 1.0f) * 2.5f;
    int iv = (int)t; if (iv > 4) iv = 4;
    float u = t - (float)iv;
    float um = 1.0f - u;
    float u2 = u * u, u3 = u2 * u;
    float N0 = um * um * um * 0.16666667f;
    float N1 = 0.5f * u3 - u2 + 0.66666667f;
    float N2 = -0.5f * u3 + 0.5f * u2 + 0.5f * u + 0.16666667f;
    float N3 = u3 * 0.16666667f;
    if (iv & 1) { r.ev0 = N1; r.ev1 = N3; r.od0 = N0; r.od1 = N2; }
    else        { r.ev0 = N0; r.ev1 = N2; r.od0 = N1; r.od1 = N3; }
    r.pe = (iv + 1) >> 1;
    r.po = iv >> 1;
    return r;
}
__device__ __forceinline__ uint32_t meta_byte(const SB& e) {
    uint32_t nE = (uint32_t)e.pe | ((uint32_t)(e.pe + 1) << 2);
    uint32_t nO = (uint32_t)e.po | ((uint32_t)(e.po + 1) << 2);
    return nE | (nO << 4);
}

__global__ void prep_A_kernel(const float* __restrict__ x) {
    int idx = blockIdx.x * blockDim.x + threadIdx.x;
    if (idx >= 512 * 8 * 512) return;
    int c = idx & 511;
    int q = (idx >> 9) & 7;
    int g = idx >> 12;
    uint32_t w16[2];
#pragma unroll
    for (int h = 0; h < 2; h++) {
        int r = 16 * g + q + 8 * h;
        float2 xv = reinterpret_cast<const float2*>(x)[(size_t)r * 512 + c];
        SB e0 = eval_point(xv.x);
        SB e1 = eval_point(xv.y);
        __half* rowp = g_Ac + (size_t)r * KCOMP;
        __half2 hs = __floats2half2_rn(e0.s, e1.s);
        reinterpret_cast<uint32_t*>(rowp)[c] = *reinterpret_cast<uint32_t*>(&hs);
        __align__(16) __half2 hv[4];
        hv[0] = __floats2half2_rn(e0.ev0, e0.ev1);
        hv[1] = __floats2half2_rn(e0.od0, e0.od1);
        hv[2] = __floats2half2_rn(e1.ev0, e1.ev1);
        hv[3] = __floats2half2_rn(e1.od0, e1.od1);
        reinterpret_cast<uint4*>(rowp + 1024)[c] = *reinterpret_cast<uint4*>(hv);
        w16[h] = meta_byte(e0) | (meta_byte(e1) << 8);
    }
    size_t mbase = ((size_t)g * 8 + q) * (KLOG / 16);
    g_M32[mbase + 128 + c] = w16[0] | (w16[1] << 16);
    if (c < 128) g_M32[mbase + c] = 0x88888888u;   // silu: idx (0,2)
}

__global__ void prep_W_kernel(const float* __restrict__ base_w,
                              const float* __restrict__ spline_w) {
    int idx = blockIdx.x * blockDim.x + threadIdx.x;
    if (idx >= OUT_F * 512) return;
    int c = idx & 511;
    int o = idx >> 9;
    __half* rowp = g_Wl + (size_t)o * KLOG;
    float2 bw = reinterpret_cast<const float2*>(base_w)[(size_t)o * 512 + c];
    __align__(8) __half h4[4];
    h4[0] = __float2half_rn(bw.x); h4[1] = __ushort_as_half(0);
    h4[2] = __float2half_rn(bw.y); h4[3] = __ushort_as_half(0);
    reinterpret_cast<uint2*>(rowp)[c] = *reinterpret_cast<uint2*>(h4);
#pragma unroll
    for (int h = 0; h < 2; h++) {
        int i = 2 * c + h;
        const float4* sp = reinterpret_cast<const float4*>(spline_w + ((size_t)o * IN_F + i) * 8);
        float4 v0 = sp[0], v1 = sp[1];
        float s[8] = {v0.x, v0.y, v0.z, v0.w, v1.x, v1.y, v1.z, v1.w};
        __align__(16) __half h8[8];
        h8[0] = __float2half_rn(s[0]); h8[1] = __float2half_rn(s[2]);
        h8[2] = __float2half_rn(s[4]); h8[3] = __float2half_rn(s[6]);
        h8[4] = __float2half_rn(s[1]); h8[5] = __float2half_rn(s[3]);
        h8[6] = __float2half_rn(s[5]); h8[7] = __float2half_rn(s[7]);
        reinterpret_cast<uint4*>(rowp + 2048)[i] = *reinterpret_cast<uint4*>(h8);
    }
}

// Bake metadata into ready-to-use e-words: g_E[(gq*NKS + s)*2 + tb].{x..w} =
// e for ks=0..3 of stage s, thread-pair parity tb. Runs after probe.
__global__ void prep_E_kernel() {
    int idx = blockIdx.x * blockDim.x + threadIdx.x;
    if (idx >= 512 * 8 * NKS * 2) return;
    int tb = idx & 1;
    int s = (idx >> 1) % NKS;
    int gq = (idx >> 1) / NKS;
    const int mode = g_meta_mode;
    const uint32_t* mp = &g_M32[(size_t)gq * (KLOG / 16) + s * 8];
    uint4 e;
    e.x = assemble_e(mode, mp[0], mp[1], tb);
    e.y = assemble_e(mode, mp[2], mp[3], tb);
    e.z = assemble_e(mode, mp[4], mp[5], tb);
    e.w = assemble_e(mode, mp[6], mp[7], tb);
    g_E[idx] = e;
}

// ===========================================================================
// Sparse GEMM: TMA producer + 8 consumers (warp tile 64x32: 2M x 4N groups),
// 4-stage ring. Stage = 128 logical k (A 64 compressed halves, B 2x64).
// ===========================================================================
#define BM 128
#define BN 128
#define NSTG 4
#define A_BYTES (BM * 64 * 2)                 // 16384
#define B_BYTES (BN * 128 * 2)                // 32768
#define STG_BYTES (A_BYTES + B_BYTES)         // 49152
#define SMEM_BARS 1024
#define SMEM_TOTAL (SMEM_BARS + NSTG * STG_BYTES)   // 197632

__global__ void __launch_bounds__(288, 1) gemm_kernel(
    const __grid_constant__ CUtensorMap tmA,
    const __grid_constant__ CUtensorMap tmB,
    float* __restrict__ C)
{
    extern __shared__ __align__(1024) char smem[];
    const uint32_t sb = smem_u32(smem);
    const uint32_t FULL  = sb;
    const uint32_t EMPTY = sb + 64;
    const uint32_t STG0  = sb + SMEM_BARS;

    const int tid = threadIdx.x;
    const int wid = tid >> 5;
    const int lane = tid & 31;
    const int bm = blockIdx.y;
    const int bn = blockIdx.x;

    if (tid == 0) {
#pragma unroll
        for (int s = 0; s < NSTG; s++) {
            MBAR_INIT(FULL + 8 * s, 1);
            MBAR_INIT(EMPTY + 8 * s, 8);
        }
    }
    __syncthreads();

    if (wid == 8) {
        if (elect_one()) {
            int st = 0, ph = 1;
            for (int s = 0; s < NKS; s++) {
                MBAR_WAIT(EMPTY + 8 * st, ph);
                const uint32_t buf = STG0 + st * STG_BYTES;
                MBAR_EXPECT_TX(FULL + 8 * st, STG_BYTES);
                tma_load_2d(buf, &tmA, s * 64, bm * BM, FULL + 8 * st);
                tma_load_2d(buf + A_BYTES, &tmB, s * 128, bn * BN, FULL + 8 * st);
                tma_load_2d(buf + A_BYTES + 16384, &tmB, s * 128 + 64, bn * BN, FULL + 8 * st);
                if (++st == NSTG) { st = 0; ph ^= 1; }
            }
        }
        return;
    }

    // consumers (warps 0..7): warp tile 64x32 -> 2 M-groups x 4 N-groups
    const int grp = lane >> 2;
    const int thr = lane & 3;
    const int tb = lane & 1;
    const int q = lane >> 2;
    const int wm = (wid & 1) * 64;
    const int wn = (wid >> 1) * 32;

    const int hiA = lane >> 4;
    const int hiB = (lane >> 3) & 1;
    uint32_t aoff[4]; int ax7[4];
#pragma unroll
    for (int im = 0; im < 4; im++) {
        int r = wm + im * 16 + (lane & 15);
        aoff[im] = (uint32_t)r * 128;
        ax7[im] = r & 7;
    }
    uint32_t boff[2]; int bx7[2];
#pragma unroll
    for (int p = 0; p < 2; p++) {
        int r = wn + p * 16 + ((lane >> 4) << 3) + (lane & 7);
        boff[p] = (uint32_t)r * 128;
        bx7[p] = r & 7;
    }
    size_t ebase[4];
#pragma unroll
    for (int im = 0; im < 4; im++) {
        int gq = (bm * 8 + (wid & 1) * 4 + im) * 8 + q;
        ebase[im] = (size_t)gq * (NKS * 2) + tb;
    }

    float acc[4][4][4];
#pragma unroll
    for (int im = 0; im < 4; im++)
#pragma unroll
        for (int in = 0; in < 4; in++)
#pragma unroll
            for (int r = 0; r < 4; r++) acc[im][in][r] = 0.0f;

    int st = 0, ph = 0;

    auto run = [&](auto selc) {
        constexpr int SEL = decltype(selc)::value;
        auto do_stage = [&](const uint4* ev) {
            uint32_t ec[16];
#pragma unroll
            for (int im = 0; im < 4; im++) {
                ec[im * 4 + 0] = ev[im].x; ec[im * 4 + 1] = ev[im].y;
                ec[im * 4 + 2] = ev[im].z; ec[im * 4 + 3] = ev[im].w;
            }
            MBAR_WAIT(FULL + 8 * st, ph);
            const uint32_t bufA = STG0 + st * STG_BYTES;
            const uint32_t bufB = bufA + A_BYTES;
#pragma unroll
            for (int ks = 0; ks < 4; ks++) {
                const int cba = 2 * ks;
                uint32_t af[4][4];
#pragma unroll
                for (int im = 0; im < 4; im++)
                    ldsm_x4(af[im], bufA + aoff[im] +
                            (uint32_t)(((cba + hiA) ^ ax7[im]) << 4));
                const uint32_t bufBs = bufB + (uint32_t)(ks >> 1) * 16384;
                const int cbl = 4 * (ks & 1);
                uint32_t bq0[2][4], bq1[2][4];
#pragma unroll
                for (int p = 0; p < 2; p++) {
                    ldsm_x4(bq0[p], bufBs + boff[p] +
                            (uint32_t)(((cbl + hiB) ^ bx7[p]) << 4));
                    ldsm_x4(bq1[p], bufBs + boff[p] +
                            (uint32_t)(((cbl + 2 + hiB) ^ bx7[p]) << 4));
                }
#pragma unroll
                for (int p = 0; p < 2; p++) {
                    uint32_t bA[4] = {bq0[p][0], bq0[p][1], bq1[p][0], bq1[p][1]};
                    uint32_t bB[4] = {bq0[p][2], bq0[p][3], bq1[p][2], bq1[p][3]};
#pragma unroll
                    for (int im = 0; im < 4; im++) {
                        mma_sp_t<SEL>(acc[im][2 * p + 0], af[im], bA, ec[im * 4 + ks]);
                        mma_sp_t<SEL>(acc[im][2 * p + 1], af[im], bB, ec[im * 4 + ks]);
                    }
                }
            }
            if (lane == 0) MBAR_ARRIVE(EMPTY + 8 * st);
            if (++st == NSTG) { st = 0; ph ^= 1; }
        };

        uint4 evA[4], evB[4];
#pragma unroll
        for (int im = 0; im < 4; im++) evA[im] = __ldg(&g_E[ebase[im]]);
#pragma unroll 1
        for (int s = 0; s < NKS; s += 2) {
#pragma unroll
            for (int im = 0; im < 4; im++)
                evB[im] = __ldg(&g_E[ebase[im] + (size_t)(s + 1) * 2]);
            do_stage(evA);
            if (s + 2 < NKS) {
#pragma unroll
                for (int im = 0; im < 4; im++)
                    evA[im] = __ldg(&g_E[ebase[im] + (size_t)(s + 2) * 2]);
            }
            do_stage(evB);
        }
    };

    if (g_meta_mode == 4) run(IC<1>{}); else run(IC<0>{});

    // epilogue
#pragma unroll
    for (int im = 0; im < 4; im++) {
        int row0 = bm * BM + wm + im * 16 + grp;
#pragma unroll
        for (int in = 0; in < 4; in++) {
            int col = bn * BN + wn + in * 8 + thr * 2;
            float2 v0 = make_float2(acc[im][in][0], acc[im][in][1]);
            float2 v1 = make_float2(acc[im][in][2], acc[im][in][3]);
            *(float2*)&C[(size_t)row0 * OUT_F + col] = v0;
            *(float2*)&C[(size_t)(row0 + 8) * OUT_F + col] = v1;
        }
    }
}

// ===========================================================================
// Host side
// ===========================================================================
typedef CUresult (*EncodeTiledFn)(
    CUtensorMap*, CUtensorMapDataType, cuuint32_t, void*,
    const cuuint64_t*, const cuuint64_t*, const cuuint32_t*, const cuuint32_t*,
    CUtensorMapInterleave, CUtensorMapSwizzle, CUtensorMapL2promotion,
    CUtensorMapFloatOOBfill);

static EncodeTiledFn get_encode_fn() {
    static EncodeTiledFn fn = nullptr;
    if (!fn) {
        void* h = dlopen("libcuda.so.1", RTLD_NOW | RTLD_GLOBAL);
        if (!h) h = dlopen("libcuda.so", RTLD_NOW | RTLD_GLOBAL);
        if (h) fn = (EncodeTiledFn)dlsym(h, "cuTensorMapEncodeTiled");
    }
    return fn;
}

static void make_map(CUtensorMap* map, void* base, uint64_t kdim, uint64_t rows,
                     uint32_t box_rows) {
    cuuint64_t dims[2]    = {(cuuint64_t)kdim, (cuuint64_t)rows};
    cuuint64_t strides[1] = {(cuuint64_t)kdim * sizeof(__half)};
    cuuint32_t box[2]     = {64u, box_rows};
    cuuint32_t estr[2]    = {1, 1};
    get_encode_fn()(map, CU_TENSOR_MAP_DATA_TYPE_FLOAT16, 2, base,
                    dims, strides, box, estr,
                    CU_TENSOR_MAP_INTERLEAVE_NONE, CU_TENSOR_MAP_SWIZZLE_128B,
                    CU_TENSOR_MAP_L2_PROMOTION_L2_128B,
                    CU_TENSOR_MAP_FLOAT_OOB_FILL_NONE);
}

extern "C" void kernel_launch(void* const* d_in, const int* in_sizes, int n_in,
                              void* d_out, int out_size) {
    const float* x        = (const float*)d_in[0];   // (8192, 1024)
    const float* base_w   = (const float*)d_in[1];   // (1024, 1024)
    const float* spline_w = (const float*)d_in[2];   // (1024, 1024, 8)
    float* out            = (float*)d_out;           // (8192, 1024)

    void *pA = nullptr, *pW = nullptr;
    cudaGetSymbolAddress(&pA, g_Ac);
    cudaGetSymbolAddress(&pW, g_Wl);

    CUtensorMap tmA, tmB;
    make_map(&tmA, pA, KCOMP, B_ROWS, BM);
    make_map(&tmB, pW, KLOG, OUT_F, BN);

    cudaFuncSetAttribute(gemm_kernel,
                         cudaFuncAttributeMaxDynamicSharedMemorySize, SMEM_TOTAL);

    probe_kernel<<<1, 32>>>();
    prep_W_kernel<<<(OUT_F * 512 + 255) / 256, 256>>>(base_w, spline_w);
    prep_A_kernel<<<(512 * 8 * 512 + 255) / 256, 256>>>(x);
    prep_E_kernel<<<(512 * 8 * NKS * 2 + 255) / 256, 256>>>();

    dim3 grid(OUT_F / BN, B_ROWS / BM);   // (8, 64)
    gemm_kernel<<<grid, 288, SMEM_TOTAL>>>(tmA, tmB, out);
}